// round 9
// baseline (speedup 1.0000x reference)
#include <cuda_runtime.h>
#include <cuda_bf16.h>
#include <math_constants.h>

// ---------------- problem constants ----------------
#define NEDGE   65536
#define NATOMS  2048
#define NRAD    24
#define NCOMP   5            // 1 two-body + 4 zeta components
#define NELEM   94
#define NEMB    16
#define NK      69           // total (lx,ly,lz) monomials across zeta=1..4
#define NSLOT   (NRAD*NK + NRAD)   // 1680 accumulation slots
#define NFEAT   216          // 24 * (1 + 2*4)
#define H1DIM   256
#define H2DIM   128
#define EB      8            // edges per accumulation batch

// ---------------- angular tables (zeta = 1,2,3,4) ----------------
__constant__ int   c_LX[NK] = {
  0,0,0,1,
  0,0,0,1, 0,0,0,1,1,2,
  0,0,0,1, 0,0,0,1,1,2, 0,0,0,0,1,1,1,2,2,3,
  0,0,0,1, 0,0,0,1,1,2, 0,0,0,0,1,1,1,2,2,3, 0,0,0,0,0,1,1,1,1,2,2,2,3,3,4 };
__constant__ int   c_LY[NK] = {
  0,0,1,0,
  0,0,1,0, 0,1,2,0,1,0,
  0,0,1,0, 0,1,2,0,1,0, 0,1,2,3,0,1,2,0,1,0,
  0,0,1,0, 0,1,2,0,1,0, 0,1,2,3,0,1,2,0,1,0, 0,1,2,3,4,0,1,2,3,0,1,2,0,1,0 };
__constant__ int   c_LZ[NK] = {
  0,1,0,0,
  0,1,0,0, 2,1,0,1,0,0,
  0,1,0,0, 2,1,0,1,0,0, 3,2,1,0,2,1,0,1,0,0,
  0,1,0,0, 2,1,0,1,0,0, 3,2,1,0,2,1,0,1,0,0, 4,3,2,1,0,3,2,1,0,2,1,0,1,0,0 };
__constant__ float c_FNORM[NK] = {
  1,1,1,1,
  1,2,2,2, 1,2,1,2,2,1,
  1,3,3,3, 3,6,3,6,6,3, 1,3,3,1,3,6,3,3,3,1,
  1,4,4,4, 6,12,6,12,12,6, 4,12,12,4,12,24,12,12,12,4,
  1,4,6,4,1, 4,12,12,4, 6,12,6, 4,4, 1 };
__constant__ float c_LAM[NK] = {
  1,-1,-1,-1,
  1,-1,-1,-1, 1,1,1,1,1,1,
  1,-1,-1,-1, 1,1,1,1,1,1, -1,-1,-1,-1,-1,-1,-1,-1,-1,-1,
  1,-1,-1,-1, 1,1,1,1,1,1, -1,-1,-1,-1,-1,-1,-1,-1,-1,-1,
  1,1,1,1,1, 1,1,1,1, 1,1,1, 1,1, 1 };
__constant__ int   c_KOFF[5] = {0, 4, 14, 34, 69};
__constant__ float c_NORMZ[4] = {1.0f, 0.5f, 0.25f, 0.125f};  // 2^{1-z}

// ---- k-tiles for the accumulation stage: 18 tiles, each inside one zeta group ----
__constant__ int c_KT0[18]   = {0, 4,8,12, 14,18,22,26,30, 34,38,42,46,50,54,58,62,66};
__constant__ int c_KTC[18]   = {4, 4,4,2,  4, 4, 4, 4, 4,  4, 4, 4, 4, 4, 4, 4, 4, 3};
__constant__ int c_KTCMP[18] = {1, 2,2,2,  3, 3, 3, 3, 3,  4, 4, 4, 4, 4, 4, 4, 4, 4};

// ---------------- scratch (static device globals; no runtime alloc) ----------------
__device__ float g_radial[NEDGE * NRAD * NCOMP];          // [E,120]
__device__ float g_feat[NATOMS * NFEAT];                  // [nat,216]
__device__ float g_embS[NELEM * NEMB];                    // per-species embedding
__device__ float g_Wt[NELEM * NFEAT * H1DIM];             // 94*216*256 precontracted
__device__ float g_h1[NATOMS * H1DIM];
__device__ float g_ebuf[NATOMS];
__device__ int   g_offs[NELEM + 1];
__device__ int   g_order[NATOMS];

__device__ __forceinline__ float silu_f(float v) {
    return __fdividef(v, 1.0f + __expf(-v));
}

// ---------------- packed f32x2 helpers (sm_103a FFMA2) ----------------
typedef unsigned long long u64t;
__device__ __forceinline__ u64t pk2(float lo, float hi) {
    u64t r; asm("mov.b64 %0, {%1,%2};" : "=l"(r) : "f"(lo), "f"(hi)); return r;
}
__device__ __forceinline__ void upk2(float& lo, float& hi, u64t v) {
    asm("mov.b64 {%0,%1}, %2;" : "=f"(lo), "=f"(hi) : "l"(v));
}
__device__ __forceinline__ void fma2(u64t& d, u64t a, u64t b) {
    asm("fma.rn.f32x2 %0, %1, %2, %3;" : "=l"(d) : "l"(a), "l"(b), "l"(d));
}

// ================= Kernel 1: per-edge radial MLP (24 -> 64 -> 120), f32x2 =================
__global__ void __launch_bounds__(256)
k_radial(const float* __restrict__ rij,
         const float* __restrict__ Wr1, const float* __restrict__ br1,
         const float* __restrict__ Wr2, const float* __restrict__ br2)
{
    __shared__ __align__(16) float sW1[NRAD * 64];
    __shared__ __align__(16) float sB1[64];
    __shared__ __align__(16) float sW2[64 * 120];
    __shared__ __align__(16) float sB2[120];
    int tid = threadIdx.x;
    for (int i = tid; i < NRAD * 64; i += 256) sW1[i] = Wr1[i];
    for (int i = tid; i < 64; i += 256)        sB1[i] = br1[i];
    for (int i = tid; i < 64 * 120; i += 256)  sW2[i] = Wr2[i];
    for (int i = tid; i < 120; i += 256)       sB2[i] = br2[i];
    __syncthreads();

    int e = blockIdx.x * 256 + tid;
    if (e >= NEDGE) return;

    float x = rij[e * 3 + 0], y = rij[e * 3 + 1], z = rij[e * 3 + 2];
    float r  = sqrtf(x * x + y * y + z * z);
    float rc = fminf(r, 6.0f);
    float fc = 0.5f * (__cosf(rc * (float)(CUDART_PI / 6.0)) + 1.0f);

    // layer 1: 24 -> 64 with packed FFMA2
    u64t h2[32];
    {
        const u64t* b2 = reinterpret_cast<const u64t*>(sB1);
        #pragma unroll
        for (int q = 0; q < 32; q++) h2[q] = b2[q];
    }
    for (int i = 0; i < NRAD; i++) {
        float d = r - (6.0f / 23.0f) * (float)i;
        float b = __expf(-8.0f * d * d) * fc;  // 1/(2*w^2) = 8, w = 0.25
        u64t bb = pk2(b, b);
        const u64t* w2 = reinterpret_cast<const u64t*>(sW1 + i * 64);
        #pragma unroll
        for (int q = 0; q < 32; q++) fma2(h2[q], bb, w2[q]);
    }
    float h[64];
    #pragma unroll
    for (int q = 0; q < 32; q++) {
        float a, b; upk2(a, b, h2[q]);
        h[2*q+0] = silu_f(a); h[2*q+1] = silu_f(b);
    }

    // layer 2: 64 -> 120 in chunks of 24 outputs (12 packed accumulators)
    for (int c = 0; c < 120; c += 24) {
        u64t o2[12];
        {
            const u64t* b2 = reinterpret_cast<const u64t*>(sB2 + c);
            #pragma unroll
            for (int j = 0; j < 12; j++) o2[j] = b2[j];
        }
        #pragma unroll
        for (int i = 0; i < 64; i++) {
            u64t hh = pk2(h[i], h[i]);
            const u64t* w2 = reinterpret_cast<const u64t*>(sW2 + i * 120 + c);
            #pragma unroll
            for (int j = 0; j < 12; j++) fma2(o2[j], hh, w2[j]);
        }
        #pragma unroll
        for (int j = 0; j < 12; j++) {
            float a, b; upk2(a, b, o2[j]);
            g_radial[e * 120 + c + 2*j + 0] = silu_f(a);
            g_radial[e * 120 + c + 2*j + 1] = silu_f(b);
        }
    }
}

// ---------------- binary search (first_atom_idx is sorted) ----------------
__device__ __forceinline__ int lower_bound_i(const int* __restrict__ a, int n, int v) {
    int lo = 0, hi = n;
    while (lo < hi) { int mid = (lo + hi) >> 1; if (a[mid] < v) lo = mid + 1; else hi = mid; }
    return lo;
}

__device__ __forceinline__ float monomial_f(int k, float ux, float uy, float uz) {
    int lx = c_LX[k], ly = c_LY[k], lz = c_LZ[k];
    float g = c_FNORM[k];
    #pragma unroll
    for (int i = 0; i < 4; i++) if (i < lx) g *= ux;
    #pragma unroll
    for (int i = 0; i < 4; i++) if (i < ly) g *= uy;
    #pragma unroll
    for (int i = 0; i < 4; i++) if (i < lz) g *= uz;
    return g;
}

// ================= Kernel 2: per-atom angular accumulation + features =================
// v3: 8 edges per single-barrier batch, warp-per-edge gij stage, 2x4 register-tiled
// accumulation (6 LDS per 8 FMA), all statically indexed (no local-memory spills).
__global__ void __launch_bounds__(256)
k_accum(const float* __restrict__ rij, const int* __restrict__ fai)
{
    __shared__ __align__(16) float s_rad[2][EB * 120];
    __shared__ float s_gij[2][EB * 70];       // [0..68]=gij, [69]=validity
    __shared__ float s_acc[NSLOT];
    __shared__ int   s_range[2];

    int a = blockIdx.x;
    int tid = threadIdx.x;
    int wid = tid >> 5, lane = tid & 31;
    if (tid == 0) {
        s_range[0] = lower_bound_i(fai, NEDGE, a);
        s_range[1] = lower_bound_i(fai, NEDGE, a + 1);
    }
    __syncthreads();
    int lo = s_range[0], hi = s_range[1];
    int nb = (hi - lo + EB - 1) / EB;

    // ---- per-thread static tile assignment ----
    bool doTile = (tid < 216);
    bool doTwo  = (tid >= 216 && tid < 240);
    int k0 = 0, kc = 0, offR = 0, rad0 = 0;
    if (doTile) {
        int rg = tid / 18, kt = tid % 18;
        k0 = c_KT0[kt]; kc = c_KTC[kt];
        rad0 = rg * 2;
        offR = rad0 * NCOMP + c_KTCMP[kt];
    } else if (doTwo) {
        rad0 = tid - 216;
        offR = rad0 * NCOMP;     // comp 0 = two-body
    }
    float a00 = 0.f, a01 = 0.f, a02 = 0.f, a03 = 0.f;
    float a10 = 0.f, a11 = 0.f, a12 = 0.f, a13 = 0.f;

    // ---- batch loader ----
    #define LOAD_BATCH(E0, BUF)                                                   \
    do {                                                                          \
        int e0_ = (E0);                                                           \
        {   /* radial: 240 float4 = 8 contiguous 120-float rows */                \
            if (tid < EB * 30) {                                                  \
                int eedge = e0_ + tid / 30;                                       \
                float4 v = make_float4(0.f, 0.f, 0.f, 0.f);                       \
                if (eedge < NEDGE)                                                \
                    v = reinterpret_cast<const float4*>(g_radial)[e0_ * 30 + tid];\
                reinterpret_cast<float4*>(s_rad[BUF])[tid] = v;                   \
            }                                                                     \
        }                                                                         \
        {   /* gij: warp w handles edge e0+w */                                   \
            int ee = e0_ + wid;                                                   \
            bool valid = (ee < hi);                                               \
            float comp = (valid && lane < 3) ? rij[ee * 3 + lane] : 0.0f;         \
            float x = __shfl_sync(0xffffffffu, comp, 0);                          \
            float y = __shfl_sync(0xffffffffu, comp, 1);                          \
            float z = __shfl_sync(0xffffffffu, comp, 2);                          \
            float inv = rsqrtf(x * x + y * y + z * z);                            \
            float ux = x * inv + 1e-12f, uy = y * inv + 1e-12f, uz = z * inv + 1e-12f; \
            float* gp = &s_gij[BUF][wid * 70];                                    \
            float g1 = valid ? monomial_f(lane, ux, uy, uz) : 0.0f;               \
            gp[lane] = g1;                                                        \
            float g2 = valid ? monomial_f(lane + 32, ux, uy, uz) : 0.0f;          \
            gp[lane + 32] = g2;                                                   \
            if (lane < 6) {                                                       \
                int k3 = lane + 64;                                               \
                float g3;                                                         \
                if (k3 == 69) g3 = valid ? 1.0f : 0.0f;                           \
                else          g3 = valid ? monomial_f(k3, ux, uy, uz) : 0.0f;     \
                gp[k3] = g3;                                                      \
            }                                                                     \
        }                                                                         \
    } while (0)

    if (nb > 0) LOAD_BATCH(lo, 0);
    __syncthreads();

    for (int t = 0; t < nb; t++) {
        int p = t & 1;
        if (t + 1 < nb) LOAD_BATCH(lo + (t + 1) * EB, p ^ 1);
        if (doTile) {
            #pragma unroll
            for (int w = 0; w < EB; w++) {
                const float* rp = &s_rad[p][w * 120];
                const float* gp = &s_gij[p][w * 70 + k0];
                float ra = rp[offR], rb = rp[offR + NCOMP];
                float g0 = gp[0], g1 = gp[1], g2 = gp[2], g3 = gp[3];
                a00 += ra * g0; a01 += ra * g1; a02 += ra * g2; a03 += ra * g3;
                a10 += rb * g0; a11 += rb * g1; a12 += rb * g2; a13 += rb * g3;
            }
        } else if (doTwo) {
            #pragma unroll
            for (int w = 0; w < EB; w++) {
                a00 += s_rad[p][w * 120 + offR] * s_gij[p][w * 70 + 69];
            }
        }
        __syncthreads();
    }
    #undef LOAD_BATCH

    // ---- write accumulators to s_acc ----
    if (doTile) {
        float* d0 = &s_acc[rad0 * NK + k0];
        float* d1 = &s_acc[(rad0 + 1) * NK + k0];
        d0[0] = a00; d1[0] = a10;
        if (kc > 1) { d0[1] = a01; d1[1] = a11; }
        if (kc > 2) { d0[2] = a02; d1[2] = a12; }
        if (kc > 3) { d0[3] = a03; d1[3] = a13; }
    } else if (doTwo) {
        s_acc[NRAD * NK + rad0] = a00;
    }
    __syncthreads();

    if (tid < NFEAT) {
        float v;
        if (tid < NRAD) {
            v = s_acc[NRAD * NK + tid];                       // two-body
        } else {
            int t = tid - NRAD;
            int iz = t / 48, sgn = (t % 48) / 24, rad = t % 24;
            int kk0 = c_KOFF[iz], kk1 = c_KOFF[iz + 1];
            float s = 0.0f;
            for (int k = kk0; k < kk1; k++) {
                float g = s_acc[rad * NK + k];
                float g2 = g * g;
                s += sgn ? g2 * c_LAM[k] : g2;
            }
            v = s * c_NORMZ[iz];
        }
        g_feat[a * NFEAT + tid] = v;
    }
}

// ================= Kernel 3: per-species embedding (94 species) =================
__global__ void k_emb(const float* __restrict__ Ws1, const float* __restrict__ bs1,
                      const float* __restrict__ Ws2, const float* __restrict__ bs2)
{
    __shared__ float t1[32];
    int s = blockIdx.x, tid = threadIdx.x;
    t1[tid] = silu_f(Ws1[s * 32 + tid] + bs1[tid]);
    __syncwarp();
    if (tid < NEMB) {
        float acc = bs2[tid];
        #pragma unroll
        for (int j = 0; j < 32; j++) acc += t1[j] * Ws2[j * NEMB + tid];
        g_embS[s * NEMB + tid] = acc;
    }
}

// ================= Kernel 4: group atoms by species (parallel atomic rank) ===========
// Within-species order is value-irrelevant (per-atom outputs depend only on the
// atom's own feature row), so an unstable atomic rank is bit-exact downstream.
__global__ void __launch_bounds__(256)
k_group(const int* __restrict__ species)
{
    __shared__ int cnt[NELEM];
    __shared__ int offs[NELEM + 1];
    __shared__ int cursor[NELEM];
    int tid = threadIdx.x;
    for (int i = tid; i < NELEM; i += 256) cnt[i] = 0;
    __syncthreads();
    for (int a = tid; a < NATOMS; a += 256) atomicAdd(&cnt[species[a]], 1);
    __syncthreads();
    if (tid == 0) {
        int run = 0;
        for (int s = 0; s < NELEM; s++) { offs[s] = run; run += cnt[s]; }
        offs[NELEM] = run;
    }
    __syncthreads();
    for (int i = tid; i <= NELEM; i += 256) g_offs[i] = offs[i];
    for (int i = tid; i < NELEM; i += 256) cursor[i] = offs[i];
    __syncthreads();
    for (int a = tid; a < NATOMS; a += 256) {
        int p = atomicAdd(&cursor[species[a]], 1);
        g_order[p] = a;
    }
}

// ================= Kernel 5: Wtilde[s,f,n] = sum_j embS[s,j] * Wa1[16f+j, n] =========
__global__ void __launch_bounds__(256)
k_wtilde(const float* __restrict__ Wa1)
{
    __shared__ float s_emb[16 * NEMB];
    int f = blockIdx.x, n = threadIdx.x;
    int s0 = blockIdx.y * 16;
    if (threadIdx.x < 16 * NEMB) {
        int s = s0 + threadIdx.x / NEMB;
        s_emb[threadIdx.x] = (s < NELEM) ? g_embS[s * NEMB + (threadIdx.x % NEMB)] : 0.0f;
    }
    float w[NEMB];
    #pragma unroll
    for (int j = 0; j < NEMB; j++) w[j] = Wa1[(f * NEMB + j) * H1DIM + n];
    __syncthreads();

    float acc[16];
    #pragma unroll
    for (int ss = 0; ss < 16; ss++) acc[ss] = 0.0f;
    #pragma unroll
    for (int j = 0; j < NEMB; j++) {
        float wj = w[j];
        #pragma unroll
        for (int ss = 0; ss < 16; ss++)
            acc[ss] += s_emb[ss * NEMB + j] * wj;
    }
    #pragma unroll
    for (int ss = 0; ss < 16; ss++) {
        int s = s0 + ss;
        if (s < NELEM)
            g_Wt[((size_t)s * NFEAT + f) * H1DIM + n] = acc[ss];
    }
}

// ================= Kernel 6: h1 = silu(feat @ Wtilde[species] + ba1), species-grouped =
__global__ void __launch_bounds__(128)
k_gemm1(const float* __restrict__ ba1)
{
    __shared__ float shf[NFEAT * 16];          // [f][a] transposed, float4-friendly
    int s = blockIdx.x;
    int n = blockIdx.y * 128 + threadIdx.x;
    int tid = threadIdx.x;
    int base = g_offs[s];
    int cnt  = g_offs[s + 1] - base;

    for (int chunk = blockIdx.z * 16; chunk < cnt; chunk += 32) {
        int m = min(16, cnt - chunk);
        for (int idx = tid; idx < NFEAT * 16; idx += 128) {
            int aq = idx / NFEAT, f = idx - aq * NFEAT;
            float v = 0.0f;
            if (aq < m) {
                int atom = g_order[base + chunk + aq];
                v = g_feat[atom * NFEAT + f];
            }
            shf[f * 16 + aq] = v;
        }
        __syncthreads();

        float acc[16];
        float b = ba1[n];
        #pragma unroll
        for (int q = 0; q < 16; q++) acc[q] = b;

        const float* wp = g_Wt + (size_t)s * NFEAT * H1DIM + n;
        #pragma unroll 1
        for (int f0 = 0; f0 < NFEAT; f0 += 8) {      // 216 = 27 * 8
            float wr[8];
            #pragma unroll
            for (int u = 0; u < 8; u++) wr[u] = wp[(size_t)(f0 + u) * H1DIM];
            #pragma unroll
            for (int u = 0; u < 8; u++) {
                float w = wr[u];
                const float4* s4 = reinterpret_cast<const float4*>(shf + (f0 + u) * 16);
                float4 a0 = s4[0], a1 = s4[1], a2 = s4[2], a3 = s4[3];
                acc[ 0] += a0.x * w; acc[ 1] += a0.y * w; acc[ 2] += a0.z * w; acc[ 3] += a0.w * w;
                acc[ 4] += a1.x * w; acc[ 5] += a1.y * w; acc[ 6] += a1.z * w; acc[ 7] += a1.w * w;
                acc[ 8] += a2.x * w; acc[ 9] += a2.y * w; acc[10] += a2.z * w; acc[11] += a2.w * w;
                acc[12] += a3.x * w; acc[13] += a3.y * w; acc[14] += a3.z * w; acc[15] += a3.w * w;
            }
        }
        for (int aq = 0; aq < m; aq++) {
            int atom = g_order[base + chunk + aq];
            g_h1[atom * H1DIM + n] = silu_f(acc[aq]);
        }
        __syncthreads();
    }
}

// ================= Kernel 7: tail MLP 256->128->1 per atom (16 atoms/block) ==========
__global__ void __launch_bounds__(128)
k_tail(const float* __restrict__ Wa2, const float* __restrict__ ba2,
       const float* __restrict__ Wa3, const float* __restrict__ ba3)
{
    __shared__ float sh[H1DIM * 16];   // [k][a]
    __shared__ float she[16 * 128];
    int a0 = blockIdx.x * 16;
    int tid = threadIdx.x;
    for (int idx = tid; idx < H1DIM * 16; idx += 128) {
        int aq = idx / H1DIM, k = idx - aq * H1DIM;
        sh[k * 16 + aq] = g_h1[(a0 + aq) * H1DIM + k];
    }
    __syncthreads();

    float acc[16];
    float b = ba2[tid];
    #pragma unroll
    for (int q = 0; q < 16; q++) acc[q] = b;
    #pragma unroll 1
    for (int k0 = 0; k0 < H1DIM; k0 += 8) {
        float wr[8];
        #pragma unroll
        for (int u = 0; u < 8; u++) wr[u] = Wa2[(k0 + u) * H2DIM + tid];
        #pragma unroll
        for (int u = 0; u < 8; u++) {
            float w = wr[u];
            const float4* s4 = reinterpret_cast<const float4*>(sh + (k0 + u) * 16);
            float4 h0 = s4[0], h1 = s4[1], h2 = s4[2], h3 = s4[3];
            acc[ 0] += h0.x * w; acc[ 1] += h0.y * w; acc[ 2] += h0.z * w; acc[ 3] += h0.w * w;
            acc[ 4] += h1.x * w; acc[ 5] += h1.y * w; acc[ 6] += h1.z * w; acc[ 7] += h1.w * w;
            acc[ 8] += h2.x * w; acc[ 9] += h2.y * w; acc[10] += h2.z * w; acc[11] += h2.w * w;
            acc[12] += h3.x * w; acc[13] += h3.y * w; acc[14] += h3.z * w; acc[15] += h3.w * w;
        }
    }
    float w3 = Wa3[tid];
    #pragma unroll
    for (int aq = 0; aq < 16; aq++) she[aq * 128 + tid] = silu_f(acc[aq]) * w3;
    __syncthreads();
    if (tid < 16) {
        float s = ba3[0];
        for (int m = 0; m < 128; m++) s += she[tid * 128 + m];
        g_ebuf[a0 + tid] = s;
    }
}

// ================= Kernel 8: deterministic tree reduction =================
__global__ void k_reduce(float* __restrict__ out)
{
    __shared__ float sr[1024];
    int tid = threadIdx.x;
    sr[tid] = g_ebuf[tid] + g_ebuf[tid + 1024];
    __syncthreads();
    for (int s = 512; s > 0; s >>= 1) {
        if (tid < s) sr[tid] += sr[tid + s];
        __syncthreads();
    }
    if (tid == 0) out[0] = sr[0];
}

// ================= launch =================
extern "C" void kernel_launch(void* const* d_in, const int* in_sizes, int n_in,
                              void* d_out, int out_size)
{
    const float* rij  = (const float*)d_in[0];
    const float* Wr1  = (const float*)d_in[1];
    const float* br1  = (const float*)d_in[2];
    const float* Wr2  = (const float*)d_in[3];
    const float* br2  = (const float*)d_in[4];
    const float* Ws1  = (const float*)d_in[5];
    const float* bs1  = (const float*)d_in[6];
    const float* Ws2  = (const float*)d_in[7];
    const float* bs2  = (const float*)d_in[8];
    const float* Wa1  = (const float*)d_in[9];
    const float* ba1  = (const float*)d_in[10];
    const float* Wa2  = (const float*)d_in[11];
    const float* ba2  = (const float*)d_in[12];
    const float* Wa3  = (const float*)d_in[13];
    const float* ba3  = (const float*)d_in[14];
    const int*   fai  = (const int*)d_in[15];
    const int*   spc  = (const int*)d_in[16];
    float* out = (float*)d_out;

    // Order chosen so the ncu single-kernel capture lands on k_accum.
    k_radial<<<NEDGE / 256, 256>>>(rij, Wr1, br1, Wr2, br2);
    k_emb<<<NELEM, 32>>>(Ws1, bs1, Ws2, bs2);
    k_group<<<1, 256>>>(spc);
    k_accum<<<NATOMS, 256>>>(rij, fai);
    k_wtilde<<<dim3(NFEAT, 6), 256>>>(Wa1);
    k_gemm1<<<dim3(NELEM, 2, 2), 128>>>(ba1);
    k_tail<<<NATOMS / 16, 128>>>(Wa2, ba2, Wa3, ba3);
    k_reduce<<<1, 1024>>>(out);
}

// round 14
// speedup vs baseline: 1.1925x; 1.1925x over previous
#include <cuda_runtime.h>
#include <cuda_bf16.h>
#include <math_constants.h>

// ---------------- problem constants ----------------
#define NEDGE   65536
#define NATOMS  2048
#define NRAD    24
#define NCOMP   5            // 1 two-body + 4 zeta components
#define NELEM   94
#define NEMB    16
#define NK      69           // total (lx,ly,lz) monomials across zeta=1..4
#define NSLOT   (NRAD*NK + NRAD)   // 1680 accumulation slots
#define NFEAT   216          // 24 * (1 + 2*4)
#define H1DIM   256
#define H2DIM   128

// ---------------- angular tables used by the feature stage ----------------
__constant__ float c_LAM[NK] = {
  1,-1,-1,-1,
  1,-1,-1,-1, 1,1,1,1,1,1,
  1,-1,-1,-1, 1,1,1,1,1,1, -1,-1,-1,-1,-1,-1,-1,-1,-1,-1,
  1,-1,-1,-1, 1,1,1,1,1,1, -1,-1,-1,-1,-1,-1,-1,-1,-1,-1,
  1,1,1,1,1, 1,1,1,1, 1,1,1, 1,1, 1 };
__constant__ int   c_KOFF[5] = {0, 4, 14, 34, 69};
__constant__ float c_NORMZ[4] = {1.0f, 0.5f, 0.25f, 0.125f};  // 2^{1-z}

// ---------------- scratch (static device globals; no runtime alloc) ----------------
__device__ float g_radT[120 * NEDGE];                     // TRANSPOSED [row][edge]
__device__ float g_gijT[NK * NEDGE];                      // TRANSPOSED [k][edge]
__device__ float g_feat[NATOMS * NFEAT];                  // [nat,216]
__device__ float g_embS[NELEM * NEMB];                    // per-species embedding
__device__ float g_Wt[NELEM * NFEAT * H1DIM];             // 94*216*256 precontracted
__device__ float g_h1[NATOMS * H1DIM];
__device__ float g_ebuf[NATOMS];
__device__ int   g_offs[NELEM + 1];
__device__ int   g_order[NATOMS];
__device__ int   g_aoffs[NATOMS + 1];                     // edge-range per atom

__device__ __forceinline__ float silu_f(float v) {
    return __fdividef(v, 1.0f + __expf(-v));
}

// ---------------- packed f32x2 helpers (sm_103a FFMA2) ----------------
typedef unsigned long long u64t;
__device__ __forceinline__ u64t pk2(float lo, float hi) {
    u64t r; asm("mov.b64 %0, {%1,%2};" : "=l"(r) : "f"(lo), "f"(hi)); return r;
}
__device__ __forceinline__ void upk2(float& lo, float& hi, u64t v) {
    asm("mov.b64 {%0,%1}, %2;" : "=f"(lo), "=f"(hi) : "l"(v));
}
__device__ __forceinline__ void fma2(u64t& d, u64t a, u64t b) {
    asm("fma.rn.f32x2 %0, %1, %2, %3;" : "=l"(d) : "l"(a), "l"(b), "l"(d));
}

// ================= Kernel 1: per-edge radial MLP (24 -> 64 -> 120), f32x2 ===========
// Output stored TRANSPOSED: g_radT[row * NEDGE + e] (coalesced per-row stores).
__global__ void __launch_bounds__(256)
k_radial(const float* __restrict__ rij,
         const float* __restrict__ Wr1, const float* __restrict__ br1,
         const float* __restrict__ Wr2, const float* __restrict__ br2)
{
    __shared__ __align__(16) float sW1[NRAD * 64];
    __shared__ __align__(16) float sB1[64];
    __shared__ __align__(16) float sW2[64 * 120];
    __shared__ __align__(16) float sB2[120];
    int tid = threadIdx.x;
    for (int i = tid; i < NRAD * 64; i += 256) sW1[i] = Wr1[i];
    for (int i = tid; i < 64; i += 256)        sB1[i] = br1[i];
    for (int i = tid; i < 64 * 120; i += 256)  sW2[i] = Wr2[i];
    for (int i = tid; i < 120; i += 256)       sB2[i] = br2[i];
    __syncthreads();

    int e = blockIdx.x * 256 + tid;
    if (e >= NEDGE) return;

    float x = rij[e * 3 + 0], y = rij[e * 3 + 1], z = rij[e * 3 + 2];
    float r  = sqrtf(x * x + y * y + z * z);
    float rc = fminf(r, 6.0f);
    float fc = 0.5f * (__cosf(rc * (float)(CUDART_PI / 6.0)) + 1.0f);

    // layer 1: 24 -> 64 with packed FFMA2
    u64t h2[32];
    {
        const u64t* b2 = reinterpret_cast<const u64t*>(sB1);
        #pragma unroll
        for (int q = 0; q < 32; q++) h2[q] = b2[q];
    }
    for (int i = 0; i < NRAD; i++) {
        float d = r - (6.0f / 23.0f) * (float)i;
        float b = __expf(-8.0f * d * d) * fc;  // 1/(2*w^2) = 8, w = 0.25
        u64t bb = pk2(b, b);
        const u64t* w2 = reinterpret_cast<const u64t*>(sW1 + i * 64);
        #pragma unroll
        for (int q = 0; q < 32; q++) fma2(h2[q], bb, w2[q]);
    }
    float h[64];
    #pragma unroll
    for (int q = 0; q < 32; q++) {
        float a, b; upk2(a, b, h2[q]);
        h[2*q+0] = silu_f(a); h[2*q+1] = silu_f(b);
    }

    // layer 2: 64 -> 120 in chunks of 24 outputs (12 packed accumulators)
    for (int c = 0; c < 120; c += 24) {
        u64t o2[12];
        {
            const u64t* b2 = reinterpret_cast<const u64t*>(sB2 + c);
            #pragma unroll
            for (int j = 0; j < 12; j++) o2[j] = b2[j];
        }
        #pragma unroll
        for (int i = 0; i < 64; i++) {
            u64t hh = pk2(h[i], h[i]);
            const u64t* w2 = reinterpret_cast<const u64t*>(sW2 + i * 120 + c);
            #pragma unroll
            for (int j = 0; j < 12; j++) fma2(o2[j], hh, w2[j]);
        }
        #pragma unroll
        for (int j = 0; j < 12; j++) {
            float a, b; upk2(a, b, o2[j]);
            g_radT[(c + 2*j + 0) * NEDGE + e] = silu_f(a);
            g_radT[(c + 2*j + 1) * NEDGE + e] = silu_f(b);
        }
    }
}

// ================= Kernel 1b: per-edge angular monomials (compile-time tables) =======
// gij[k](e) = FNORM[k] * ux^LX * uy^LY * uz^LZ, stored transposed [k][e] (coalesced).
__global__ void __launch_bounds__(256)
k_gij(const float* __restrict__ rij)
{
    int e = blockIdx.x * 256 + threadIdx.x;
    if (e >= NEDGE) return;
    float x = rij[e * 3 + 0], y = rij[e * 3 + 1], z = rij[e * 3 + 2];
    float inv = rsqrtf(x * x + y * y + z * z);
    float ux = x * inv + 1e-12f, uy = y * inv + 1e-12f, uz = z * inv + 1e-12f;

    float PX[5], PY[5], PZ[5];
    PX[0] = 1.f; PY[0] = 1.f; PZ[0] = 1.f;
    #pragma unroll
    for (int i = 1; i < 5; i++) { PX[i] = PX[i-1]*ux; PY[i] = PY[i-1]*uy; PZ[i] = PZ[i-1]*uz; }

    // local const tables -> fully folded under #pragma unroll (no constant-port traffic)
    const int LX[NK] = {
      0,0,0,1, 0,0,0,1,0,0,0,1,1,2,
      0,0,0,1,0,0,0,1,1,2,0,0,0,0,1,1,1,2,2,3,
      0,0,0,1,0,0,0,1,1,2,0,0,0,0,1,1,1,2,2,3,0,0,0,0,0,1,1,1,1,2,2,2,3,3,4 };
    const int LY[NK] = {
      0,0,1,0, 0,0,1,0,0,1,2,0,1,0,
      0,0,1,0,0,1,2,0,1,0,0,1,2,3,0,1,2,0,1,0,
      0,0,1,0,0,1,2,0,1,0,0,1,2,3,0,1,2,0,1,0,0,1,2,3,4,0,1,2,3,0,1,2,0,1,0 };
    const int LZ[NK] = {
      0,1,0,0, 2,1,0,1,0,0,
      3,2,1,0,2,1,0,1,0,0, 3,2,1,0,2,1,0,1,0,0,
      4,3,2,1,0,3,2,1,0,2,1,0,1,0,0, 4,3,2,1,0,3,2,1,0,2,1,0,1,0,0 };
    // NOTE: LZ above must match (LX,LY): recompute properly as n - lx - ly per group.
    const float FN[NK] = {
      1,1,1,1,
      1,2,2,2, 1,2,1,2,2,1,
      1,3,3,3, 3,6,3,6,6,3, 1,3,3,1,3,6,3,3,3,1,
      1,4,4,4, 6,12,6,12,12,6, 4,12,12,4,12,24,12,12,12,4,
      1,4,6,4,1, 4,12,12,4, 6,12,6, 4,4, 1 };
    // Correct LZ derived from the enumeration (lx+ly+lz = n), kept explicit:
    const int LZc[NK] = {
      0,1,0,0,
      0,1,0,0, 2,1,0,1,0,0,
      0,1,0,0, 2,1,0,1,0,0, 3,2,1,0,2,1,0,1,0,0,
      0,1,0,0, 2,1,0,1,0,0, 3,2,1,0,2,1,0,1,0,0, 4,3,2,1,0,3,2,1,0,2,1,0,1,0,0 };
    const int LXc[NK] = {
      0,0,0,1,
      0,0,0,1, 0,0,0,1,1,2,
      0,0,0,1, 0,0,0,1,1,2, 0,0,0,0,1,1,1,2,2,3,
      0,0,0,1, 0,0,0,1,1,2, 0,0,0,0,1,1,1,2,2,3, 0,0,0,0,0,1,1,1,1,2,2,2,3,3,4 };
    const int LYc[NK] = {
      0,0,1,0,
      0,0,1,0, 0,1,2,0,1,0,
      0,0,1,0, 0,1,2,0,1,0, 0,1,2,3,0,1,2,0,1,0,
      0,0,1,0, 0,1,2,0,1,0, 0,1,2,3,0,1,2,0,1,0, 0,1,2,3,4,0,1,2,3,0,1,2,0,1,0 };
    (void)LX; (void)LY; (void)LZ;

    #pragma unroll
    for (int k = 0; k < NK; k++)
        g_gijT[k * NEDGE + e] = FN[k] * PX[LXc[k]] * PY[LYc[k]] * PZ[LZc[k]];
}

// ================= Kernel 1c: per-atom edge ranges (2049 parallel binary searches) ===
__device__ __forceinline__ int lower_bound_i(const int* __restrict__ a, int n, int v) {
    int lo = 0, hi = n;
    while (lo < hi) { int mid = (lo + hi) >> 1; if (a[mid] < v) lo = mid + 1; else hi = mid; }
    return lo;
}
__global__ void k_bounds(const int* __restrict__ fai)
{
    int a = blockIdx.x * 256 + threadIdx.x;
    if (a <= NATOMS) g_aoffs[a] = lower_bound_i(fai, NEDGE, a);
}

// ================= Kernel 2: per-atom angular accumulation + features (v4) ===========
// Warp-autonomous: each warp owns slots s == wid (mod 8). For each slot, lanes read
// 32 consecutive edges of radT[row]/gijT[k] from global (coalesced, L1-resident),
// FMA, then one butterfly reduction per slot (8 interleaved for ILP). No barriers
// until the feature stage, no smem staging, no divergent constant loads.
__global__ void __launch_bounds__(256)
k_accum()
{
    __shared__ float s_acc[NSLOT];
    int a = blockIdx.x;
    int tid = threadIdx.x;
    int wid = tid >> 5, lane = tid & 31;
    int lo = g_aoffs[a], hi = g_aoffs[a + 1];

    // slot cursor: s = wid + 8*t, t = 0..215 ; incremental (rad,k) tracking
    int s = wid;
    int rad = 0, k = wid;              // wid < 8 < 69 so rad=0, k=wid initially
    for (int grp = 0; grp < 27; grp++) {
        int sg = s;                    // first slot of this group
        int rowj[8], kkj[8];           // kkj: >=0 gij row, -1 two-body, -2 inactive
        #pragma unroll
        for (int j = 0; j < 8; j++) {
            if (s < NRAD * NK) {
                int iz = (k < 4) ? 1 : ((k < 14) ? 2 : ((k < 34) ? 3 : 4));
                rowj[j] = rad * NCOMP + iz;
                kkj[j] = k;
            } else if (s < NSLOT) {
                rowj[j] = (s - NRAD * NK) * NCOMP;   // two-body component row
                kkj[j] = -1;
            } else {
                rowj[j] = 0; kkj[j] = -2;
            }
            s += 8; k += 8; if (k >= NK) { k -= NK; rad++; }
        }

        float acc[8];
        #pragma unroll
        for (int j = 0; j < 8; j++) acc[j] = 0.0f;

        for (int c = lo; c < hi; c += 32) {
            int e = c + lane;
            bool v = (e < hi);
            #pragma unroll
            for (int j = 0; j < 8; j++) {
                if (kkj[j] == -2) continue;
                float rv = v ? g_radT[rowj[j] * NEDGE + e] : 0.0f;
                float gv = (kkj[j] >= 0) ? (v ? g_gijT[kkj[j] * NEDGE + e] : 0.0f) : 1.0f;
                acc[j] += rv * gv;
            }
        }

        #pragma unroll
        for (int off = 16; off > 0; off >>= 1) {
            #pragma unroll
            for (int j = 0; j < 8; j++)
                acc[j] += __shfl_xor_sync(0xffffffffu, acc[j], off);
        }
        if (lane == 0) {
            #pragma unroll
            for (int j = 0; j < 8; j++) {
                int sj = sg + 8 * j;
                if (sj < NSLOT) s_acc[sj] = acc[j];
            }
        }
    }
    __syncthreads();

    if (tid < NFEAT) {
        float v;
        if (tid < NRAD) {
            v = s_acc[NRAD * NK + tid];                       // two-body
        } else {
            int t = tid - NRAD;
            int iz = t / 48, sgn = (t % 48) / 24, radq = t % 24;
            int kk0 = c_KOFF[iz], kk1 = c_KOFF[iz + 1];
            float sacc = 0.0f;
            for (int kq = kk0; kq < kk1; kq++) {
                float g = s_acc[radq * NK + kq];
                float g2 = g * g;
                sacc += sgn ? g2 * c_LAM[kq] : g2;
            }
            v = sacc * c_NORMZ[iz];
        }
        g_feat[a * NFEAT + tid] = v;
    }
}

// ================= Kernel 3: per-species embedding (94 species) =================
__global__ void k_emb(const float* __restrict__ Ws1, const float* __restrict__ bs1,
                      const float* __restrict__ Ws2, const float* __restrict__ bs2)
{
    __shared__ float t1[32];
    int s = blockIdx.x, tid = threadIdx.x;
    t1[tid] = silu_f(Ws1[s * 32 + tid] + bs1[tid]);
    __syncwarp();
    if (tid < NEMB) {
        float acc = bs2[tid];
        #pragma unroll
        for (int j = 0; j < 32; j++) acc += t1[j] * Ws2[j * NEMB + tid];
        g_embS[s * NEMB + tid] = acc;
    }
}

// ================= Kernel 4: group atoms by species (parallel atomic rank) ===========
__global__ void __launch_bounds__(256)
k_group(const int* __restrict__ species)
{
    __shared__ int cnt[NELEM];
    __shared__ int offs[NELEM + 1];
    __shared__ int cursor[NELEM];
    int tid = threadIdx.x;
    for (int i = tid; i < NELEM; i += 256) cnt[i] = 0;
    __syncthreads();
    for (int a = tid; a < NATOMS; a += 256) atomicAdd(&cnt[species[a]], 1);
    __syncthreads();
    if (tid == 0) {
        int run = 0;
        for (int s = 0; s < NELEM; s++) { offs[s] = run; run += cnt[s]; }
        offs[NELEM] = run;
    }
    __syncthreads();
    for (int i = tid; i <= NELEM; i += 256) g_offs[i] = offs[i];
    for (int i = tid; i < NELEM; i += 256) cursor[i] = offs[i];
    __syncthreads();
    for (int a = tid; a < NATOMS; a += 256) {
        int p = atomicAdd(&cursor[species[a]], 1);
        g_order[p] = a;
    }
}

// ================= Kernel 5: Wtilde[s,f,n] = sum_j embS[s,j] * Wa1[16f+j, n] =========
__global__ void __launch_bounds__(256)
k_wtilde(const float* __restrict__ Wa1)
{
    __shared__ float s_emb[16 * NEMB];
    int f = blockIdx.x, n = threadIdx.x;
    int s0 = blockIdx.y * 16;
    if (threadIdx.x < 16 * NEMB) {
        int s = s0 + threadIdx.x / NEMB;
        s_emb[threadIdx.x] = (s < NELEM) ? g_embS[s * NEMB + (threadIdx.x % NEMB)] : 0.0f;
    }
    float w[NEMB];
    #pragma unroll
    for (int j = 0; j < NEMB; j++) w[j] = Wa1[(f * NEMB + j) * H1DIM + n];
    __syncthreads();

    float acc[16];
    #pragma unroll
    for (int ss = 0; ss < 16; ss++) acc[ss] = 0.0f;
    #pragma unroll
    for (int j = 0; j < NEMB; j++) {
        float wj = w[j];
        #pragma unroll
        for (int ss = 0; ss < 16; ss++)
            acc[ss] += s_emb[ss * NEMB + j] * wj;
    }
    #pragma unroll
    for (int ss = 0; ss < 16; ss++) {
        int s = s0 + ss;
        if (s < NELEM)
            g_Wt[((size_t)s * NFEAT + f) * H1DIM + n] = acc[ss];
    }
}

// ================= Kernel 6: h1 = silu(feat @ Wtilde[species] + ba1), species-grouped =
__global__ void __launch_bounds__(128)
k_gemm1(const float* __restrict__ ba1)
{
    __shared__ float shf[NFEAT * 16];          // [f][a] transposed, float4-friendly
    int s = blockIdx.x;
    int n = blockIdx.y * 128 + threadIdx.x;
    int tid = threadIdx.x;
    int base = g_offs[s];
    int cnt  = g_offs[s + 1] - base;

    for (int chunk = blockIdx.z * 16; chunk < cnt; chunk += 32) {
        int m = min(16, cnt - chunk);
        for (int idx = tid; idx < NFEAT * 16; idx += 128) {
            int aq = idx / NFEAT, f = idx - aq * NFEAT;
            float v = 0.0f;
            if (aq < m) {
                int atom = g_order[base + chunk + aq];
                v = g_feat[atom * NFEAT + f];
            }
            shf[f * 16 + aq] = v;
        }
        __syncthreads();

        float acc[16];
        float b = ba1[n];
        #pragma unroll
        for (int q = 0; q < 16; q++) acc[q] = b;

        const float* wp = g_Wt + (size_t)s * NFEAT * H1DIM + n;
        #pragma unroll 1
        for (int f0 = 0; f0 < NFEAT; f0 += 8) {      // 216 = 27 * 8
            float wr[8];
            #pragma unroll
            for (int u = 0; u < 8; u++) wr[u] = wp[(size_t)(f0 + u) * H1DIM];
            #pragma unroll
            for (int u = 0; u < 8; u++) {
                float w = wr[u];
                const float4* s4 = reinterpret_cast<const float4*>(shf + (f0 + u) * 16);
                float4 a0 = s4[0], a1 = s4[1], a2 = s4[2], a3 = s4[3];
                acc[ 0] += a0.x * w; acc[ 1] += a0.y * w; acc[ 2] += a0.z * w; acc[ 3] += a0.w * w;
                acc[ 4] += a1.x * w; acc[ 5] += a1.y * w; acc[ 6] += a1.z * w; acc[ 7] += a1.w * w;
                acc[ 8] += a2.x * w; acc[ 9] += a2.y * w; acc[10] += a2.z * w; acc[11] += a2.w * w;
                acc[12] += a3.x * w; acc[13] += a3.y * w; acc[14] += a3.z * w; acc[15] += a3.w * w;
            }
        }
        for (int aq = 0; aq < m; aq++) {
            int atom = g_order[base + chunk + aq];
            g_h1[atom * H1DIM + n] = silu_f(acc[aq]);
        }
        __syncthreads();
    }
}

// ================= Kernel 7: tail MLP 256->128->1 per atom (16 atoms/block) ==========
__global__ void __launch_bounds__(128)
k_tail(const float* __restrict__ Wa2, const float* __restrict__ ba2,
       const float* __restrict__ Wa3, const float* __restrict__ ba3)
{
    __shared__ float sh[H1DIM * 16];   // [k][a]
    __shared__ float she[16 * 128];
    int a0 = blockIdx.x * 16;
    int tid = threadIdx.x;
    for (int idx = tid; idx < H1DIM * 16; idx += 128) {
        int aq = idx / H1DIM, k = idx - aq * H1DIM;
        sh[k * 16 + aq] = g_h1[(a0 + aq) * H1DIM + k];
    }
    __syncthreads();

    float acc[16];
    float b = ba2[tid];
    #pragma unroll
    for (int q = 0; q < 16; q++) acc[q] = b;
    #pragma unroll 1
    for (int k0 = 0; k0 < H1DIM; k0 += 8) {
        float wr[8];
        #pragma unroll
        for (int u = 0; u < 8; u++) wr[u] = Wa2[(k0 + u) * H2DIM + tid];
        #pragma unroll
        for (int u = 0; u < 8; u++) {
            float w = wr[u];
            const float4* s4 = reinterpret_cast<const float4*>(sh + (k0 + u) * 16);
            float4 h0 = s4[0], h1 = s4[1], h2 = s4[2], h3 = s4[3];
            acc[ 0] += h0.x * w; acc[ 1] += h0.y * w; acc[ 2] += h0.z * w; acc[ 3] += h0.w * w;
            acc[ 4] += h1.x * w; acc[ 5] += h1.y * w; acc[ 6] += h1.z * w; acc[ 7] += h1.w * w;
            acc[ 8] += h2.x * w; acc[ 9] += h2.y * w; acc[10] += h2.z * w; acc[11] += h2.w * w;
            acc[12] += h3.x * w; acc[13] += h3.y * w; acc[14] += h3.z * w; acc[15] += h3.w * w;
        }
    }
    float w3 = Wa3[tid];
    #pragma unroll
    for (int aq = 0; aq < 16; aq++) she[aq * 128 + tid] = silu_f(acc[aq]) * w3;
    __syncthreads();
    if (tid < 16) {
        float s = ba3[0];
        for (int m = 0; m < 128; m++) s += she[tid * 128 + m];
        g_ebuf[a0 + tid] = s;
    }
}

// ================= Kernel 8: deterministic tree reduction =================
__global__ void k_reduce(float* __restrict__ out)
{
    __shared__ float sr[1024];
    int tid = threadIdx.x;
    sr[tid] = g_ebuf[tid] + g_ebuf[tid + 1024];
    __syncthreads();
    for (int s = 512; s > 0; s >>= 1) {
        if (tid < s) sr[tid] += sr[tid + s];
        __syncthreads();
    }
    if (tid == 0) out[0] = sr[0];
}

// ================= launch =================
extern "C" void kernel_launch(void* const* d_in, const int* in_sizes, int n_in,
                              void* d_out, int out_size)
{
    const float* rij  = (const float*)d_in[0];
    const float* Wr1  = (const float*)d_in[1];
    const float* br1  = (const float*)d_in[2];
    const float* Wr2  = (const float*)d_in[3];
    const float* br2  = (const float*)d_in[4];
    const float* Ws1  = (const float*)d_in[5];
    const float* bs1  = (const float*)d_in[6];
    const float* Ws2  = (const float*)d_in[7];
    const float* bs2  = (const float*)d_in[8];
    const float* Wa1  = (const float*)d_in[9];
    const float* ba1  = (const float*)d_in[10];
    const float* Wa2  = (const float*)d_in[11];
    const float* ba2  = (const float*)d_in[12];
    const float* Wa3  = (const float*)d_in[13];
    const float* ba3  = (const float*)d_in[14];
    const int*   fai  = (const int*)d_in[15];
    const int*   spc  = (const int*)d_in[16];
    float* out = (float*)d_out;

    // Order chosen so the ncu single-kernel capture (skip 5, count 1) lands on k_accum.
    k_radial<<<NEDGE / 256, 256>>>(rij, Wr1, br1, Wr2, br2);
    k_gij<<<NEDGE / 256, 256>>>(rij);
    k_bounds<<<(NATOMS + 256) / 256, 256>>>(fai);
    k_accum<<<NATOMS, 256>>>();
    k_emb<<<NELEM, 32>>>(Ws1, bs1, Ws2, bs2);
    k_group<<<1, 256>>>(spc);
    k_wtilde<<<dim3(NFEAT, 6), 256>>>(Wa1);
    k_gemm1<<<dim3(NELEM, 2, 2), 128>>>(ba1);
    k_tail<<<NATOMS / 16, 128>>>(Wa2, ba2, Wa3, ba3);
    k_reduce<<<1, 1024>>>(out);
}